// round 1
// baseline (speedup 1.0000x reference)
#include <cuda_runtime.h>
#include <math_constants.h>

#define S_LEN 1500
#define BATCHN 2
#define NH 8
#define DM 16
#define DFF 128
#define NROWS (BATCHN * S_LEN)          // 3000
#define XELEMS (NROWS * DM)             // 48000

// Scratch (no allocations allowed in kernel_launch)
__device__ float g_x[XELEMS];
__device__ float g_q[BATCHN * NH * S_LEN * 2];
__device__ float g_k[BATCHN * NH * S_LEN * 2];
__device__ float g_v[BATCHN * NH * S_LEN * 2];
__device__ float g_ctx[XELEMS];

// x = enc * src_w + src_b + PE(s,d)
__global__ void embed_kernel(const float* __restrict__ enc,
                             const float* __restrict__ srcw,
                             const float* __restrict__ srcb)
{
    int idx = blockIdx.x * blockDim.x + threadIdx.x;
    if (idx >= XELEMS) return;
    int d = idx & 15;
    int s = (idx >> 4) % S_LEN;
    int b = idx / (S_LEN * DM);
    const float c = -0.57564627324851148f;   // -ln(10000)/16
    float dv = expf((float)(d & ~1) * c);
    float phase = (float)s * dv;
    float pe = (d & 1) ? cosf(phase) : sinf(phase);
    g_x[idx] = enc[b * S_LEN + s] * srcw[d] + srcb[d] + pe;
}

// q,k,v = x @ W{q,k,v}, stored as [B,H,S,2]
__global__ void qkv_kernel(const float* __restrict__ Wq,
                           const float* __restrict__ Wk,
                           const float* __restrict__ Wv)
{
    int idx = blockIdx.x * blockDim.x + threadIdx.x;
    if (idx >= XELEMS) return;
    int col = idx & 15;
    int bs = idx >> 4;
    int b = bs / S_LEN, s = bs - b * S_LEN;
    const float* xr = g_x + bs * DM;
    float q = 0.f, k = 0.f, v = 0.f;
#pragma unroll
    for (int m = 0; m < DM; m++) {
        float xv = xr[m];
        q = fmaf(xv, Wq[m * 16 + col], q);
        k = fmaf(xv, Wk[m * 16 + col], k);
        v = fmaf(xv, Wv[m * 16 + col], v);
    }
    int h = col >> 1, dk = col & 1;
    int o = ((b * NH + h) * S_LEN + s) * 2 + dk;
    g_q[o] = q; g_k[o] = k; g_v[o] = v;
}

// One block per (b*8+h, query-chunk). K/V resident in SMEM.
// Each warp: one query row at a time -> scores, online max, exp, attn write
// (float4 STG), ctx accumulate.
#define QPB 79
__global__ void __launch_bounds__(256) attn_kernel(float* __restrict__ attn_out)
{
    __shared__ float2 sk[S_LEN];
    __shared__ float2 sv[S_LEN];
    int bh = blockIdx.x;                 // b*8 + h
    int tid = threadIdx.x;
    const float2* kp = ((const float2*)g_k) + bh * S_LEN;
    const float2* vp = ((const float2*)g_v) + bh * S_LEN;
    for (int i = tid; i < S_LEN; i += 256) { sk[i] = kp[i]; sv[i] = vp[i]; }
    __syncthreads();

    int warp = tid >> 5, lane = tid & 31;
    int q0 = blockIdx.y * QPB;
    int qend = min(q0 + QPB, S_LEN);
    int b = bh >> 3, h = bh & 7;
    const float scale = 0.70710678118654752f;   // 1/sqrt(2)

    for (int q = q0 + warp; q < qend; q += 8) {
        float2 qv = ((const float2*)g_q)[bh * S_LEN + q];
        float4 e[12];                       // scores, then exp values
        float m = -CUDART_INF_F;
#pragma unroll
        for (int i = 0; i < 12; i++) {
            int i4 = lane + 32 * i;         // covers keys 4*i4 .. 4*i4+3
            float4 s4;
            if (i4 < 375) {
                float2 k0 = sk[4 * i4 + 0];
                float2 k1 = sk[4 * i4 + 1];
                float2 k2 = sk[4 * i4 + 2];
                float2 k3 = sk[4 * i4 + 3];
                s4.x = (qv.x * k0.x + qv.y * k0.y) * scale;
                s4.y = (qv.x * k1.x + qv.y * k1.y) * scale;
                s4.z = (qv.x * k2.x + qv.y * k2.y) * scale;
                s4.w = (qv.x * k3.x + qv.y * k3.y) * scale;
            } else {
                s4 = make_float4(-CUDART_INF_F, -CUDART_INF_F,
                                 -CUDART_INF_F, -CUDART_INF_F);
            }
            e[i] = s4;
            m = fmaxf(m, fmaxf(fmaxf(s4.x, s4.y), fmaxf(s4.z, s4.w)));
        }
#pragma unroll
        for (int o = 16; o; o >>= 1)
            m = fmaxf(m, __shfl_xor_sync(0xffffffffu, m, o));

        float sum = 0.f, c0 = 0.f, c1 = 0.f;
#pragma unroll
        for (int i = 0; i < 12; i++) {
            int i4 = lane + 32 * i;
            if (i4 < 375) {
                float4 s4 = e[i];
                float4 ee;
                ee.x = __expf(s4.x - m);
                ee.y = __expf(s4.y - m);
                ee.z = __expf(s4.z - m);
                ee.w = __expf(s4.w - m);
                float2 v0 = sv[4 * i4 + 0];
                float2 v1 = sv[4 * i4 + 1];
                float2 v2 = sv[4 * i4 + 2];
                float2 v3 = sv[4 * i4 + 3];
                sum += (ee.x + ee.y) + (ee.z + ee.w);
                c0 = fmaf(ee.x, v0.x, fmaf(ee.y, v1.x, fmaf(ee.z, v2.x, fmaf(ee.w, v3.x, c0))));
                c1 = fmaf(ee.x, v0.y, fmaf(ee.y, v1.y, fmaf(ee.z, v2.y, fmaf(ee.w, v3.y, c1))));
                e[i] = ee;
            }
        }
#pragma unroll
        for (int o = 16; o; o >>= 1) {
            sum += __shfl_xor_sync(0xffffffffu, sum, o);
            c0  += __shfl_xor_sync(0xffffffffu, c0, o);
            c1  += __shfl_xor_sync(0xffffffffu, c1, o);
        }
        float r = 1.0f / sum;

        float4* orow = (float4*)(attn_out + ((size_t)bh * S_LEN + q) * S_LEN);
#pragma unroll
        for (int i = 0; i < 12; i++) {
            int i4 = lane + 32 * i;
            if (i4 < 375) {
                float4 ee = e[i];
                ee.x *= r; ee.y *= r; ee.z *= r; ee.w *= r;
                orow[i4] = ee;
            }
        }
        if (lane == 0) {
            int base = (b * S_LEN + q) * DM + h * 2;
            g_ctx[base]     = c0 * r;
            g_ctx[base + 1] = c1 * r;
        }
    }
}

// x = LN(ctx@Wo + x); x = LN(relu(x@W1)@W2 + x). Block = 8 rows x 16 dims.
__global__ void __launch_bounds__(128) post_kernel(const float* __restrict__ Wo,
                                                   const float* __restrict__ W1,
                                                   const float* __restrict__ W2,
                                                   float* __restrict__ outx,
                                                   int writeOut)
{
    __shared__ float swo[DM * DM];
    __shared__ float sw1[DM * DFF];
    __shared__ float sw2[DFF * DM];
    __shared__ float st[8][DM];
    __shared__ float sh[8][DFF];
    __shared__ float sx[8][DM];
    __shared__ float sc[8][DM];

    int tid = threadIdx.x;
    for (int i = tid; i < DM * DM; i += 128) swo[i] = Wo[i];
    for (int i = tid; i < DM * DFF; i += 128) sw1[i] = W1[i];
    for (int i = tid; i < DFF * DM; i += 128) sw2[i] = W2[i];

    int r = tid >> 4, d = tid & 15;
    int grow = blockIdx.x * 8 + r;            // < 3000 = 375*8
    sx[r][d] = g_x[grow * DM + d];
    sc[r][d] = g_ctx[grow * DM + d];
    __syncthreads();

    // ctx @ Wo + x
    float s1 = sx[r][d];
#pragma unroll
    for (int k = 0; k < DM; k++) s1 = fmaf(sc[r][k], swo[k * 16 + d], s1);

    // LayerNorm over 16-lane group
    float mean = s1;
#pragma unroll
    for (int o = 8; o; o >>= 1) mean += __shfl_xor_sync(0xffffffffu, mean, o);
    mean *= (1.0f / 16.0f);
    float dv = s1 - mean;
    float var = dv * dv;
#pragma unroll
    for (int o = 8; o; o >>= 1) var += __shfl_xor_sync(0xffffffffu, var, o);
    var *= (1.0f / 16.0f);
    float t = dv * rsqrtf(var + 1e-5f);
    st[r][d] = t;
    __syncthreads();

    // h = relu(t @ W1): each thread does 8 of the 128 hidden units
#pragma unroll
    for (int i = 0; i < 8; i++) {
        int j = d + 16 * i;
        float hv = 0.f;
#pragma unroll
        for (int k = 0; k < DM; k++) hv = fmaf(st[r][k], sw1[k * DFF + j], hv);
        sh[r][j] = fmaxf(hv, 0.f);
    }
    __syncthreads();

    // out = LN(h @ W2 + t)
    float s2 = t;
#pragma unroll
    for (int j = 0; j < DFF; j++) s2 = fmaf(sh[r][j], sw2[j * 16 + d], s2);

    float mean2 = s2;
#pragma unroll
    for (int o = 8; o; o >>= 1) mean2 += __shfl_xor_sync(0xffffffffu, mean2, o);
    mean2 *= (1.0f / 16.0f);
    float dv2 = s2 - mean2;
    float var2 = dv2 * dv2;
#pragma unroll
    for (int o = 8; o; o >>= 1) var2 += __shfl_xor_sync(0xffffffffu, var2, o);
    var2 *= (1.0f / 16.0f);
    float t2 = dv2 * rsqrtf(var2 + 1e-5f);

    float* xo = writeOut ? outx : g_x;
    xo[grow * DM + d] = t2;
}

extern "C" void kernel_launch(void* const* d_in, const int* in_sizes, int n_in,
                              void* d_out, int out_size)
{
    const float* enc  = (const float*)d_in[0];
    const float* srcw = (const float*)d_in[1];
    const float* srcb = (const float*)d_in[2];
    const float* Wq   = (const float*)d_in[3];
    const float* Wk   = (const float*)d_in[4];
    const float* Wv   = (const float*)d_in[5];
    const float* Wo   = (const float*)d_in[6];
    const float* W1   = (const float*)d_in[7];
    const float* W2   = (const float*)d_in[8];
    float* out = (float*)d_out;

    embed_kernel<<<(XELEMS + 255) / 256, 256>>>(enc, srcw, srcb);
    for (int l = 0; l < 3; l++) {
        qkv_kernel<<<(XELEMS + 255) / 256, 256>>>(Wq + l * 256, Wk + l * 256, Wv + l * 256);
        attn_kernel<<<dim3(BATCHN * NH, (S_LEN + QPB - 1) / QPB), 256>>>(
            out + XELEMS + (size_t)l * (size_t)BATCHN * NH * S_LEN * S_LEN);
        post_kernel<<<NROWS / 8, 128>>>(Wo + l * 256, W1 + l * 2048, W2 + l * 2048,
                                        out, l == 2 ? 1 : 0);
    }
}